// round 5
// baseline (speedup 1.0000x reference)
#include <cuda_runtime.h>
#include <cstdint>

#define BB 4
#define AA 9
#define HH 50
#define WW 76
#define NN (AA * HH * WW)          // 34200 boxes per image
#define PRE 4000
#define POST 300
#define SORTN 4096                 // slow path sort size
#define FASTN 2048                 // fast path sort size
#define NMS_THR 0.7f
#define NBINS 2048
#define FBATCH 256

// ---------------- static scratch ----------------
__device__ float4   d_props[BB * NN];
__device__ unsigned d_keys [BB * NN];
__device__ unsigned d_hist [BB * NBINS];   // zero at load; fast_kernel re-zeroes each run
__device__ int      d_slow [BB];

// ---------------- helpers ----------------
__device__ __forceinline__ float areaf(float4 b) {
    return __fmul_rn(__fsub_rn(b.z, b.x), __fsub_rn(b.w, b.y));
}

__device__ __forceinline__ bool iou_gt(float4 a, float aA, float4 b, float aB) {
    float xx1 = fmaxf(a.x, b.x);
    float yy1 = fmaxf(a.y, b.y);
    float xx2 = fminf(a.z, b.z);
    float yy2 = fminf(a.w, b.w);
    float w = fmaxf(__fsub_rn(xx2, xx1), 0.0f);
    float h = fmaxf(__fsub_rn(yy2, yy1), 0.0f);
    float inter = __fmul_rn(w, h);
    float denom = __fadd_rn(__fsub_rn(__fadd_rn(aA, aB), inter), 1e-9f);
    return __fdiv_rn(inter, denom) > NMS_THR;
}

// register compare-exchange via warp shuffle (stride < 32)
__device__ __forceinline__ unsigned long long cex_shfl(unsigned long long v, int t,
                                                       bool asc, unsigned s) {
    unsigned long long pv = __shfl_xor_sync(0xffffffffu, v, s);
    bool lower = ((t & (int)s) == 0);
    bool takeMin = (asc == lower);
    bool pickP = takeMin ? (pv < v) : (pv > v);
    return pickP ? pv : v;
}

// ---------------- 1) decode + key + shared-agg histogram + prefill ----------------
__global__ void decode_kernel(const float* __restrict__ scores,
                              const float* __restrict__ deltas,
                              const float* __restrict__ im_info,
                              const float* __restrict__ anchors,
                              float* __restrict__ out) {
    __shared__ unsigned shist[NBINS];
    const int tid = threadIdx.x;
    const int b = blockIdx.y;
    const int i = blockIdx.x * 256 + tid;

    #pragma unroll
    for (int r = 0; r < NBINS / 256; r++) shist[tid + r * 256] = 0;

    // prefill out rows to [b, 0, 0, 0, 0]
    int g = (b * gridDim.x + blockIdx.x) * 256 + tid;
    if (g < BB * POST * 5) {
        int col = g % 5;
        int bb = g / (POST * 5);
        out[g] = (col == 0) ? (float)bb : 0.0f;
    }
    __syncthreads();

    if (i < NN) {
        int a = i % AA;
        int p = i / AA;
        int x = p % WW;
        int y = p / WW;

        float sx = (float)(x * 16);
        float sy = (float)(y * 16);
        float ax1 = __fadd_rn(anchors[a * 4 + 0], sx);
        float ay1 = __fadd_rn(anchors[a * 4 + 1], sy);
        float ax2 = __fadd_rn(anchors[a * 4 + 2], sx);
        float ay2 = __fadd_rn(anchors[a * 4 + 3], sy);

        float w  = __fadd_rn(__fsub_rn(ax2, ax1), 1.0f);
        float h  = __fadd_rn(__fsub_rn(ay2, ay1), 1.0f);
        float cx = __fadd_rn(ax1, __fmul_rn(0.5f, w));
        float cy = __fadd_rn(ay1, __fmul_rn(0.5f, h));

        const int HW = HH * WW;
        size_t dbase = ((size_t)b * 4 * AA + a * 4) * HW + (size_t)y * WW + x;
        float dx  = deltas[dbase];
        float dy  = deltas[dbase + HW];
        float dz  = deltas[dbase + 2 * HW];
        float dw_ = deltas[dbase + 3 * HW];

        float pcx = __fadd_rn(__fmul_rn(dx, w), cx);
        float pcy = __fadd_rn(__fmul_rn(dy, h), cy);
        float pw  = __fmul_rn(expf(dz),  w);
        float ph  = __fmul_rn(expf(dw_), h);

        float x1 = __fsub_rn(pcx, __fmul_rn(0.5f, pw));
        float y1 = __fsub_rn(pcy, __fmul_rn(0.5f, ph));
        float x2 = __fadd_rn(pcx, __fmul_rn(0.5f, pw));
        float y2 = __fadd_rn(pcy, __fmul_rn(0.5f, ph));

        float hiw = __fsub_rn(im_info[b * 3 + 1], 1.0f);
        float hih = __fsub_rn(im_info[b * 3 + 0], 1.0f);
        x1 = fminf(fmaxf(x1, 0.0f), hiw);
        y1 = fminf(fmaxf(y1, 0.0f), hih);
        x2 = fminf(fmaxf(x2, 0.0f), hiw);
        y2 = fminf(fmaxf(y2, 0.0f), hih);

        int t = b * NN + i;
        d_props[t] = make_float4(x1, y1, x2, y2);

        float s = scores[((size_t)b * AA + a) * HW + (size_t)y * WW + x];
        unsigned bits = __float_as_uint(s);
        unsigned key = (bits & 0x80000000u) ? ~bits : (bits | 0x80000000u);
        d_keys[t] = key;
        atomicAdd(&shist[key >> 21], 1u);
    }
    __syncthreads();
    #pragma unroll
    for (int r = 0; r < NBINS / 256; r++) {
        int bin = tid + r * 256;
        unsigned c = shist[bin];
        if (c) atomicAdd(&d_hist[b * NBINS + bin], c);
    }
}

// ---------------- shared-mem NMS state (fast path) ----------------
struct NmsStateF {
    float4 kbox[POST];
    float  karea[POST];
    float4 cbox[FBATCH];
    float  carea[FBATCH];
    __align__(16) unsigned mat[FBATCH][8];   // suppression matrix rows (256 bits)
    unsigned dead[8];                        // 256-bit dead mask
};
struct NmsState64 {
    float4 kbox[POST];
    float  karea[POST];
    float4 cbox[64];
    float  carea[64];
    int    flags[64];
};
union SharedFast { unsigned hist[NBINS]; NmsStateF n; };
union SharedSlow { unsigned hist[2048]; NmsState64 n; };

// ---------------- 2) FAST: coarse select + hybrid sort-2048 + matrix NMS ----------------
__global__ void __launch_bounds__(1024) fast_kernel(float* __restrict__ out) {
    const int img = blockIdx.x;
    const unsigned* keys = d_keys + (size_t)img * NN;
    const int tid = threadIdx.x;

    __shared__ unsigned long long sh_sort[FASTN];
    __shared__ SharedFast u;
    __shared__ unsigned csum[64];
    __shared__ unsigned cursor, sh_cnt, sh_T;
    __shared__ int kept_sh;

    // ---- read precomputed histogram, zero it for the next replay ----
    unsigned* ghist = d_hist + img * NBINS;
    #pragma unroll
    for (int rep = 0; rep < NBINS / 1024; rep++) {
        int i = tid + rep * 1024;
        u.hist[i] = ghist[i];
        ghist[i] = 0;
    }
    __syncthreads();
    if (tid < 64) {
        unsigned s = 0;
        #pragma unroll
        for (int v = 0; v < 32; v++) s += u.hist[tid * 32 + v];
        csum[tid] = s;
    }
    __syncthreads();
    if (tid == 0) {
        unsigned cum = 0;
        int ch = 63;
        for (; ch > 0; ch--) {
            if (cum + csum[ch] >= 1024u) break;
            cum += csum[ch];
        }
        int bsel = ch * 32;
        for (int v = ch * 32 + 31; v >= ch * 32; v--) {
            if (cum + u.hist[v] >= 1024u) { bsel = v; break; }
            cum += u.hist[v];
        }
        sh_T = (unsigned)bsel << 21;
        sh_cnt = cum + u.hist[bsel];
        cursor = 0;
        kept_sh = 0;
    }
    __syncthreads();
    const unsigned T = sh_T;
    const unsigned cnt = sh_cnt;

    if (cnt > FASTN) {
        if (tid == 0) d_slow[img] = 1;
        return;
    }

    // ---- unordered compaction of every key >= T ----
    sh_sort[tid] = 0xFFFFFFFFFFFFFFFFull;
    sh_sort[tid + 1024] = 0xFFFFFFFFFFFFFFFFull;
    __syncthreads();
    for (int i = tid; i < NN; i += 1024) {
        unsigned k = keys[i];
        if (k >= T) {
            unsigned pos = atomicAdd(&cursor, 1u);
            sh_sort[pos] = (((unsigned long long)(~k)) << 32) | (unsigned)i;
        }
    }
    __syncthreads();

    // ---- hybrid bitonic sort ascending on (~key, idx) ----
    {
        unsigned long long v0 = sh_sort[tid];
        unsigned long long v1 = sh_sort[tid + 1024];
        // stage A: sizes 2..32, all strides < 32 -> register shuffles
        #pragma unroll
        for (unsigned size = 2; size <= 32; size <<= 1) {
            bool asc = ((tid & (int)size) == 0);
            #pragma unroll
            for (unsigned s = size >> 1; s > 0; s >>= 1) {
                v0 = cex_shfl(v0, tid, asc, s);
                v1 = cex_shfl(v1, tid, asc, s);
            }
        }
        sh_sort[tid] = v0;
        sh_sort[tid + 1024] = v1;
        __syncthreads();
        // stage B: sizes 64..2048
        for (unsigned size = 64; size <= FASTN; size <<= 1) {
            for (unsigned stride = size >> 1; stride >= 32; stride >>= 1) {
                #pragma unroll
                for (int rep = 0; rep < 2; rep++) {
                    int t = tid + rep * 1024;
                    int l = t ^ (int)stride;
                    if (l > t) {
                        unsigned long long a = sh_sort[t], b = sh_sort[l];
                        bool asc = ((t & (int)size) == 0);
                        if ((a > b) == asc) { sh_sort[t] = b; sh_sort[l] = a; }
                    }
                }
                __syncthreads();
            }
            // register finish: strides 16..1
            v0 = sh_sort[tid];
            v1 = sh_sort[tid + 1024];
            bool asc0 = ((tid & (int)size) == 0);
            bool asc1 = (((tid + 1024) & (int)size) == 0);
            #pragma unroll
            for (unsigned s = 16; s > 0; s >>= 1) {
                v0 = cex_shfl(v0, tid, asc0, s);
                v1 = cex_shfl(v1, tid, asc1, s);
            }
            sh_sort[tid] = v0;
            sh_sort[tid + 1024] = v1;
            __syncthreads();
        }
    }

    // ---- batch-256 greedy NMS with suppression bit-matrix ----
    int kept = 0;
    const float4* props = d_props + (size_t)img * NN;

    for (int base = 0; base < (int)cnt && kept < POST; base += FBATCH) {
        // clear matrix + dead mask
        #pragma unroll
        for (int rep = 0; rep < 2; rep++)
            ((unsigned*)u.n.mat)[tid + rep * 1024] = 0u;
        if (tid < 8) u.n.dead[tid] = 0u;
        __syncthreads();

        // load candidates (mark padding dead)
        if (tid < FBATCH) {
            int ci = base + tid;
            if (ci < (int)cnt) {
                unsigned idx = (unsigned)(sh_sort[ci] & 0xFFFFFFFFull);
                float4 bx = props[idx];
                u.n.cbox[tid]  = bx;
                u.n.carea[tid] = areaf(bx);
            } else {
                u.n.cbox[tid]  = make_float4(0.f, 0.f, 0.f, 0.f);
                u.n.carea[tid] = 0.f;
                atomicOr(&u.n.dead[tid >> 5], 1u << (tid & 31));
            }
        }
        __syncthreads();

        // phase 1: candidates vs kept list
        for (int p = tid; p < FBATCH * kept; p += 1024) {
            int c = p & (FBATCH - 1), ki = p >> 8;
            if (iou_gt(u.n.cbox[c], u.n.carea[c], u.n.kbox[ki], u.n.karea[ki]))
                atomicOr(&u.n.dead[c >> 5], 1u << (c & 31));
        }
        // phase 1b: 256x256 pair matrix (upper triangle)
        #pragma unroll
        for (int rep = 0; rep < 64; rep++) {
            int p = tid + rep * 1024;
            int r = p >> 8, c = p & (FBATCH - 1);
            if (c > r &&
                iou_gt(u.n.cbox[r], u.n.carea[r], u.n.cbox[c], u.n.carea[c]))
                atomicOr(&u.n.mat[r][c >> 5], 1u << (c & 31));
        }
        __syncthreads();

        // phase 2: serial greedy via bit masks on thread 0
        if (tid == 0) {
            unsigned long long rem[4];
            #pragma unroll
            for (int j = 0; j < 4; j++)
                rem[j] = ~(((unsigned long long)u.n.dead[2 * j + 1] << 32) |
                           (unsigned long long)u.n.dead[2 * j]);
            int kl = kept;
            #pragma unroll
            for (int j = 0; j < 4; j++) {
                while (rem[j] && kl < POST) {
                    int c64 = __ffsll((long long)rem[j]) - 1;
                    int c = j * 64 + c64;
                    float4 cc = u.n.cbox[c];
                    u.n.kbox[kl]  = cc;
                    u.n.karea[kl] = u.n.carea[c];
                    float* o = out + ((size_t)img * POST + kl) * 5;
                    o[1] = cc.x; o[2] = cc.y; o[3] = cc.z; o[4] = cc.w;
                    kl++;
                    uint4 m0 = *(const uint4*)&u.n.mat[c][0];
                    uint4 m1 = *(const uint4*)&u.n.mat[c][4];
                    rem[0] &= ~(((unsigned long long)m0.y << 32) | m0.x);
                    rem[1] &= ~(((unsigned long long)m0.w << 32) | m0.z);
                    rem[2] &= ~(((unsigned long long)m1.y << 32) | m1.x);
                    rem[3] &= ~(((unsigned long long)m1.w << 32) | m1.z);
                    rem[j] &= ~(1ull << c64);
                }
                if (kl >= POST) break;
            }
            kept_sh = kl;
        }
        __syncthreads();
        kept = kept_sh;
    }

    if (tid == 0) d_slow[img] = (kept < POST) ? 1 : 0;
}

// ---------------- 3) SLOW fallback: full select-4000 + sort-4096 + NMS ----------------
__global__ void __launch_bounds__(1024) slow_kernel(float* __restrict__ out) {
    const int img = blockIdx.x;
    if (d_slow[img] == 0) return;

    const unsigned* keys = d_keys + (size_t)img * NN;
    const int tid = threadIdx.x;
    const int lane = tid & 31, wid = tid >> 5;

    __shared__ unsigned long long sh_sort[SORTN];
    __shared__ SharedSlow u;
    __shared__ unsigned csum[64];
    __shared__ unsigned warpsum[32];
    __shared__ unsigned sh_bucket, sh_need, cursor, eqbase, chunk_total;
    __shared__ int kept_sh;

    if (tid == 0) sh_need = PRE;

    unsigned prefix = 0, pmask = 0;
    const int shifts[3]  = {21, 10, 0};
    const int nbins3[3]  = {2048, 2048, 1024};
    for (int r = 0; r < 3; r++) {
        const int shift = shifts[r];
        const unsigned bmask = (unsigned)nbins3[r] - 1u;
        for (int i = tid; i < 2048; i += 1024) u.hist[i] = 0;
        __syncthreads();
        for (int i = tid; i < NN; i += 1024) {
            unsigned k = keys[i];
            if ((k & pmask) == prefix) atomicAdd(&u.hist[(k >> shift) & bmask], 1u);
        }
        __syncthreads();
        const int nch = nbins3[r] >> 5;
        if (tid < nch) {
            unsigned s = 0;
            for (int v = 0; v < 32; v++) s += u.hist[tid * 32 + v];
            csum[tid] = s;
        }
        __syncthreads();
        if (tid == 0) {
            unsigned nd = sh_need, cum = 0;
            int ch = nch - 1;
            for (; ch > 0; ch--) {
                if (cum + csum[ch] >= nd) break;
                cum += csum[ch];
            }
            int bsel = ch * 32;
            for (int v = ch * 32 + 31; v >= ch * 32; v--) {
                if (cum + u.hist[v] >= nd) { bsel = v; break; }
                cum += u.hist[v];
            }
            sh_bucket = (unsigned)bsel;
            sh_need = nd - cum;
        }
        __syncthreads();
        prefix |= (sh_bucket << shift);
        pmask  |= (bmask << shift);
        __syncthreads();
    }
    const unsigned T = prefix;
    const unsigned need_eq = sh_need;

    if (tid == 0) { cursor = 0; eqbase = 0; }
    for (int i = tid; i < SORTN; i += 1024)
        sh_sort[i] = 0xFFFFFFFFFFFFFFFFull;
    __syncthreads();

    for (int base = 0; base < NN; base += 1024) {
        int i = base + tid;
        unsigned k = (i < NN) ? keys[i] : 0u;
        unsigned isgt = (i < NN && k > T) ? 1u : 0u;
        unsigned iseq = (i < NN && k == T) ? 1u : 0u;

        unsigned v = iseq;
        #pragma unroll
        for (int off = 1; off < 32; off <<= 1) {
            unsigned tmp = __shfl_up_sync(0xffffffffu, v, off);
            if (lane >= off) v += tmp;
        }
        if (lane == 31) warpsum[wid] = v;
        __syncthreads();
        if (wid == 0) {
            unsigned wv = warpsum[lane];
            unsigned vv = wv;
            #pragma unroll
            for (int off = 1; off < 32; off <<= 1) {
                unsigned tmp = __shfl_up_sync(0xffffffffu, vv, off);
                if (lane >= off) vv += tmp;
            }
            warpsum[lane] = vv - wv;
            if (lane == 31) chunk_total = vv;
        }
        __syncthreads();
        unsigned excl = v - iseq + warpsum[wid];
        unsigned eqrank = eqbase + excl;
        bool take = isgt || (iseq && eqrank < need_eq);
        if (take) {
            unsigned pos = atomicAdd(&cursor, 1u);
            sh_sort[pos] = (((unsigned long long)(~k)) << 32) | (unsigned)i;
        }
        __syncthreads();
        if (tid == 0) eqbase += chunk_total;
        __syncthreads();
    }

    unsigned prev_stride = 0xFFFFu;
    for (unsigned size = 2; size <= SORTN; size <<= 1) {
        for (unsigned stride = size >> 1; stride > 0; stride >>= 1) {
            if (stride >= 32 || prev_stride >= 32) __syncthreads();
            else __syncwarp();
            #pragma unroll
            for (int rep = 0; rep < SORTN / 1024; rep++) {
                int t = tid + rep * 1024;
                int l = t ^ (int)stride;
                if (l > t) {
                    unsigned long long a = sh_sort[t], b = sh_sort[l];
                    bool asc = ((t & (int)size) == 0);
                    if ((a > b) == asc) { sh_sort[t] = b; sh_sort[l] = a; }
                }
            }
            prev_stride = stride;
        }
    }

    if (tid == 0) kept_sh = 0;
    __syncthreads();
    int kept = 0;
    const float4* props = d_props + (size_t)img * NN;

    for (int base = 0; base < PRE; base += 64) {
        if (tid < 64) {
            int ci = base + tid;
            if (ci < PRE) {
                unsigned idx = (unsigned)(sh_sort[ci] & 0xFFFFFFFFull);
                float4 bx = props[idx];
                u.n.cbox[tid]  = bx;
                u.n.carea[tid] = areaf(bx);
                u.n.flags[tid] = 0;
            } else {
                u.n.cbox[tid]  = make_float4(0.f, 0.f, 0.f, 0.f);
                u.n.carea[tid] = 0.f;
                u.n.flags[tid] = 1;
            }
        }
        __syncthreads();

        for (int p = tid; p < 64 * kept; p += 1024) {
            int c = p & 63, ki = p >> 6;
            if (iou_gt(u.n.cbox[c], u.n.carea[c], u.n.kbox[ki], u.n.karea[ki]))
                u.n.flags[c] = 1;
        }
        __syncthreads();

        if (tid < 32) {
            const int l = tid;
            float4 b0 = u.n.cbox[l],      b1 = u.n.cbox[l + 32];
            float  a0 = u.n.carea[l],     a1 = u.n.carea[l + 32];
            unsigned f0 = __ballot_sync(0xffffffffu, u.n.flags[l] != 0);
            unsigned f1 = __ballot_sync(0xffffffffu, u.n.flags[l + 32] != 0);
            unsigned long long rem = ~(((unsigned long long)f1 << 32) | (unsigned long long)f0);
            int kl = kept;
            while (rem && kl < POST) {
                int c = __ffsll((long long)rem) - 1;
                rem &= rem - 1;
                float4 cc = u.n.cbox[c];
                float  ca = u.n.carea[c];
                if (l == 0) {
                    u.n.kbox[kl]  = cc;
                    u.n.karea[kl] = ca;
                    float* o = out + ((size_t)img * POST + kl) * 5;
                    o[1] = cc.x; o[2] = cc.y; o[3] = cc.z; o[4] = cc.w;
                }
                kl++;
                bool s0 = (l > c)        && iou_gt(cc, ca, b0, a0);
                bool s1 = ((l + 32) > c) && iou_gt(cc, ca, b1, a1);
                unsigned m0 = __ballot_sync(0xffffffffu, s0);
                unsigned m1 = __ballot_sync(0xffffffffu, s1);
                rem &= ~(((unsigned long long)m1 << 32) | (unsigned long long)m0);
            }
            if (l == 0) kept_sh = kl;
        }
        __syncthreads();
        kept = kept_sh;
        if (kept >= POST) break;
    }
}

// ---------------- launch ----------------
extern "C" void kernel_launch(void* const* d_in, const int* in_sizes, int n_in,
                              void* d_out, int out_size) {
    const float* scores  = (const float*)d_in[0];
    const float* deltas  = (const float*)d_in[1];
    const float* im_info = (const float*)d_in[2];
    const float* anchors = (const float*)d_in[3];
    float* out = (float*)d_out;

    dim3 dgrid((NN + 255) / 256, BB);
    decode_kernel<<<dgrid, 256>>>(scores, deltas, im_info, anchors, out);
    fast_kernel<<<BB, 1024>>>(out);
    slow_kernel<<<BB, 1024>>>(out);
}